// round 2
// baseline (speedup 1.0000x reference)
#include <cuda_runtime.h>
#include <math.h>

// Model dims
#define SEQ   1024
#define DM    768
#define DI    1536
#define DS    16
#define DTR   48
#define VOCAB 50280

// ---------------- scratch buffers (device globals; no allocation) ------------
__device__ float g_x  [SEQ * DM];
__device__ float g_res[SEQ * DM];
__device__ float g_lres[SEQ * DM];
__device__ float g_h  [SEQ * DM];
__device__ float g_xz [SEQ * 2 * DI];
__device__ float g_xs [SEQ * DI];
__device__ float g_dbc[SEQ * 80];
__device__ float g_dt [SEQ * DI];
__device__ float g_yz [SEQ * DI];

// ---------------- init: embedding gather + zero residual ---------------------
__global__ void k_init(const int* __restrict__ ids, const float* __restrict__ emb)
{
    int i = blockIdx.x * blockDim.x + threadIdx.x;
    if (i < SEQ * DM) {
        int t = i / DM, c = i - t * DM;
        g_x[i]   = emb[(size_t)ids[t] * DM + c];
        g_res[i] = 0.f;
    }
}

__global__ void k_copy_lres()
{
    int i = blockIdx.x * blockDim.x + threadIdx.x;
    if (i < SEQ * DM) g_lres[i] = g_res[i];
}

__global__ void k_add_lres()
{
    int i = blockIdx.x * blockDim.x + threadIdx.x;
    if (i < SEQ * DM) g_res[i] += g_lres[i];
}

// ---------------- fused residual add + RMSNorm --------------------------------
// res += x ; h = res * rsqrt(mean(res^2)+eps) * w
__global__ void __launch_bounds__(256) k_addnorm(const float* __restrict__ w)
{
    int r = blockIdx.x;
    int tid = threadIdx.x;
    float v[3];
    float ss = 0.f;
#pragma unroll
    for (int j = 0; j < 3; j++) {
        int c = tid + j * 256;
        float t = g_x[r * DM + c] + g_res[r * DM + c];
        g_res[r * DM + c] = t;
        v[j] = t;
        ss += t * t;
    }
#pragma unroll
    for (int o = 16; o; o >>= 1) ss += __shfl_xor_sync(0xffffffffu, ss, o);
    __shared__ float red[8];
    __shared__ float scale;
    if ((tid & 31) == 0) red[tid >> 5] = ss;
    __syncthreads();
    if (tid == 0) {
        float s = 0.f;
#pragma unroll
        for (int i = 0; i < 8; i++) s += red[i];
        scale = rsqrtf(s * (1.0f / DM) + 1e-5f);
    }
    __syncthreads();
    float sc = scale;
#pragma unroll
    for (int j = 0; j < 3; j++) {
        int c = tid + j * 256;
        g_h[r * DM + c] = v[j] * sc * w[c];
    }
}

// ---------------- SGEMM: C[M,N] = A[M,K] * B[N,K]^T (NT, fp32) ----------------
// 128x128 block, BK=8, 256 threads, 8x8 per thread, float4 smem loads.
// mode 1: C = softplus(C + bias[n])
__global__ void __launch_bounds__(256) sgemm_nt(
    const float* __restrict__ A, const float* __restrict__ B, float* __restrict__ C,
    int N, int K, int lda, int ldb, int ldc,
    const float* __restrict__ bias, int mode)
{
    __shared__ float As[8][132];
    __shared__ float Bs[8][132];
    int tid = threadIdx.x;
    int bm = blockIdx.y << 7;
    int bn = blockIdx.x << 7;
    int lr = tid >> 1;           // 0..127
    int lk = (tid & 1) << 2;     // 0 or 4
    const float* Ag = A + (size_t)(bm + lr) * lda + lk;
    int brow = bn + lr;
    const float* Bg = B + (size_t)brow * ldb + lk;
    bool bvalid = brow < N;
    int tx = tid & 15, ty = tid >> 4;

    float acc[8][8];
#pragma unroll
    for (int i = 0; i < 8; i++)
#pragma unroll
        for (int j = 0; j < 8; j++) acc[i][j] = 0.f;

    for (int k0 = 0; k0 < K; k0 += 8) {
        float4 av = *(const float4*)(Ag + k0);
        float4 bv = make_float4(0.f, 0.f, 0.f, 0.f);
        if (bvalid) bv = *(const float4*)(Bg + k0);
        As[lk + 0][lr] = av.x; As[lk + 1][lr] = av.y;
        As[lk + 2][lr] = av.z; As[lk + 3][lr] = av.w;
        Bs[lk + 0][lr] = bv.x; Bs[lk + 1][lr] = bv.y;
        Bs[lk + 2][lr] = bv.z; Bs[lk + 3][lr] = bv.w;
        __syncthreads();
#pragma unroll
        for (int k = 0; k < 8; k++) {
            float4 a0 = *(const float4*)&As[k][ty << 3];
            float4 a1 = *(const float4*)&As[k][(ty << 3) + 4];
            float4 b0 = *(const float4*)&Bs[k][tx << 3];
            float4 b1 = *(const float4*)&Bs[k][(tx << 3) + 4];
            float ar[8] = {a0.x, a0.y, a0.z, a0.w, a1.x, a1.y, a1.z, a1.w};
            float br[8] = {b0.x, b0.y, b0.z, b0.w, b1.x, b1.y, b1.z, b1.w};
#pragma unroll
            for (int i = 0; i < 8; i++)
#pragma unroll
                for (int j = 0; j < 8; j++)
                    acc[i][j] = fmaf(ar[i], br[j], acc[i][j]);
        }
        __syncthreads();
    }

#pragma unroll
    for (int i = 0; i < 8; i++) {
        int m = bm + (ty << 3) + i;
#pragma unroll
        for (int j = 0; j < 8; j++) {
            int n = bn + (tx << 3) + j;
            if (n < N) {
                float vv = acc[i][j];
                if (mode == 1) {
                    vv += bias[n];
                    vv = (vv > 15.f) ? vv : log1pf(__expf(vv));
                }
                C[(size_t)m * ldc + n] = vv;
            }
        }
    }
}

// ---------------- depthwise causal conv (K=4) + SiLU --------------------------
__global__ void k_conv(const float* __restrict__ cw, const float* __restrict__ cb)
{
    int i = blockIdx.x * blockDim.x + threadIdx.x;
    if (i >= SEQ * DI) return;
    int t = i / DI, d = i - t * DI;
    float s = cb[d];
    const float* w = cw + d * 4;
#pragma unroll
    for (int j = 0; j < 4; j++) {
        int tt = t - 3 + j;
        if (tt >= 0) s = fmaf(w[j], g_xz[tt * (2 * DI) + d], s);
    }
    g_xs[i] = s / (1.f + __expf(-s));
}

// ---------------- x_proj: dbc[m, 0:80] = xs[m,:] @ x_proj_w^T -----------------
// one block per row; A row cached in smem; warp-per-output dot products.
__global__ void __launch_bounds__(256) k_xproj(const float* __restrict__ Bw)
{
    int m = blockIdx.x;
    __shared__ float ar[DI];
    for (int i = threadIdx.x; i < DI; i += 256) ar[i] = g_xs[m * DI + i];
    __syncthreads();
    int w = threadIdx.x >> 5, lane = threadIdx.x & 31;
    for (int n = w; n < 80; n += 8) {
        const float* bp = Bw + n * DI;
        float acc = 0.f;
        for (int k = lane; k < DI; k += 32) acc = fmaf(ar[k], bp[k], acc);
#pragma unroll
        for (int o = 16; o; o >>= 1) acc += __shfl_xor_sync(0xffffffffu, acc, o);
        if (lane == 0) g_dbc[m * 80 + n] = acc;
    }
}

// ---------------- selective scan + D skip + SiLU gate --------------------------
// thread = (channel d, state n); 16 lanes form one channel group.
__global__ void __launch_bounds__(256) k_scan(const float* __restrict__ Alog,
                                              const float* __restrict__ Dp)
{
    int tid = threadIdx.x;
    int grp = tid >> 4;          // 16 channels per block
    int n = tid & 15;
    int d = blockIdx.x * 16 + grp;

    float A  = -__expf(Alog[d * DS + n]);
    float Dd = Dp[d];
    float h = 0.f;

    const float* dtp = g_dt + d;
    const float* xsp = g_xs + d;
    const float* zp  = g_xz + DI + d;    // gate half
    const float* bp  = g_dbc + 48 + n;
    const float* cp  = g_dbc + 64 + n;
    float* yo = g_yz + d;

    for (int t = 0; t < SEQ; t++) {
        float a  = dtp[t * DI];
        float x  = xsp[t * DI];
        float Bv = bp[t * 80];
        float Cv = cp[t * 80];
        float dA = __expf(a * A);
        h = fmaf(dA, h, a * Bv * x);
        float yp = h * Cv;
        yp += __shfl_xor_sync(0xffffffffu, yp, 8);
        yp += __shfl_xor_sync(0xffffffffu, yp, 4);
        yp += __shfl_xor_sync(0xffffffffu, yp, 2);
        yp += __shfl_xor_sync(0xffffffffu, yp, 1);
        if (n == 0) {
            float z = zp[t * 2 * DI];
            float y = fmaf(Dd, x, yp);
            yo[t * DI] = y * (z / (1.f + __expf(-z)));
        }
    }
}

// ---------------- host orchestration ------------------------------------------
extern "C" void kernel_launch(void* const* d_in, const int* in_sizes, int n_in,
                              void* d_out, int out_size)
{
    (void)in_sizes; (void)n_in; (void)out_size;
    const int*   ids   = (const int*)  d_in[0];
    const float* emb   = (const float*)d_in[1];
    const float* inw   = (const float*)d_in[2];
    const float* convw = (const float*)d_in[3];
    const float* convb = (const float*)d_in[4];
    const float* xpw   = (const float*)d_in[5];
    const float* dtw   = (const float*)d_in[6];
    const float* dtb   = (const float*)d_in[7];
    const float* alog  = (const float*)d_in[8];
    const float* Dp    = (const float*)d_in[9];
    const float* outw  = (const float*)d_in[10];
    const float* nw    = (const float*)d_in[11];
    const float* nfw   = (const float*)d_in[12];
    const float* lmw   = (const float*)d_in[13];
    float* out = (float*)d_out;

    static float *p_h = nullptr, *p_xz = nullptr, *p_dbc = nullptr,
                 *p_dt = nullptr, *p_yz = nullptr, *p_x = nullptr;
    if (!p_h) {
        cudaGetSymbolAddress((void**)&p_h,   g_h);
        cudaGetSymbolAddress((void**)&p_xz,  g_xz);
        cudaGetSymbolAddress((void**)&p_dbc, g_dbc);
        cudaGetSymbolAddress((void**)&p_dt,  g_dt);
        cudaGetSymbolAddress((void**)&p_yz,  g_yz);
        cudaGetSymbolAddress((void**)&p_x,   g_x);
    }

    const int EW = (SEQ * DM) / 256;       // 3072 blocks of 256

    k_init<<<EW, 256>>>(ids, emb);

    for (int step = 0; step < 28; step++) {
        int li = (step < 22) ? step : 22 + ((step - 22) & 1);
        if (step >= 22 && ((step - 22) & 1) == 0)
            k_copy_lres<<<EW, 256>>>();

        // residual add + norm -> g_h
        k_addnorm<<<SEQ, 256>>>(nw + (size_t)li * DM);

        // in_proj: g_xz = g_h @ W^T   (1024 x 3072, K=768)
        sgemm_nt<<<dim3((2 * DI) / 128, SEQ / 128), 256>>>(
            p_h, inw + (size_t)li * 2 * DI * DM, p_xz,
            2 * DI, DM, DM, DM, 2 * DI, nullptr, 0);

        // depthwise conv + silu -> g_xs
        k_conv<<<(SEQ * DI) / 256, 256>>>(convw + (size_t)li * DI * 4,
                                          convb + (size_t)li * DI);

        // x_proj -> g_dbc (1024 x 80, K=1536)
        k_xproj<<<SEQ, 256>>>(xpw + (size_t)li * 80 * DI);

        // dt = softplus(dbc[:, :48] @ dt_w^T + b)  (1024 x 1536, K=48)
        sgemm_nt<<<dim3(DI / 128, SEQ / 128), 256>>>(
            p_dbc, dtw + (size_t)li * DI * DTR, p_dt,
            DI, DTR, 80, DTR, DI, dtb + (size_t)li * DI, 1);

        // selective scan + gate -> g_yz
        k_scan<<<DI / 16, 256>>>(alog + (size_t)li * DI * DS,
                                 Dp + (size_t)li * DI);

        // out_proj: g_x = g_yz @ W^T  (1024 x 768, K=1536)
        sgemm_nt<<<dim3(DM / 128, SEQ / 128), 256>>>(
            p_yz, outw + (size_t)li * DM * DI, p_x,
            DM, DI, DI, DI, DM, nullptr, 0);

        if (step >= 22 && ((step - 22) & 1) == 1)
            k_add_lres<<<EW, 256>>>();
    }

    // final fused add-norm -> g_h
    k_addnorm<<<SEQ, 256>>>(nfw);

    // lm_head: out = g_h @ lm_head_w^T  (1024 x 50280, K=768)
    sgemm_nt<<<dim3((VOCAB + 127) / 128, SEQ / 128), 256>>>(
        p_h, lmw, out, VOCAB, DM, DM, DM, VOCAB, nullptr, 0);
}

// round 4
// speedup vs baseline: 1.3841x; 1.3841x over previous
#include <cuda_runtime.h>
#include <cuda_bf16.h>
#include <math.h>
#include <stdint.h>

// Model dims
#define SEQ   1024
#define DM    768
#define DI    1536
#define DS    16
#define DTR   48
#define VOCAB 50280

// ---------------- scratch buffers (device globals; no allocation) ------------
__device__ float g_x  [SEQ * DM];
__device__ float g_res[SEQ * DM];
__device__ float g_lres[SEQ * DM];
__device__ float g_h  [SEQ * DM];
__device__ float g_xz [SEQ * 2 * DI];
__device__ float g_xs [SEQ * DI];
__device__ float g_dbc[SEQ * 80];
__device__ float g_dt [SEQ * DI];
__device__ float g_yz [SEQ * DI];

// bf16 3-term split buffers
__device__ __nv_bfloat16 g_abf [SEQ * 3 * DI];          // activations, up to K'=4608
__device__ __nv_bfloat16 g_wbf [(2 * DI) * 3 * DM];     // per-layer weights
__device__ __nv_bfloat16 g_lmbf[VOCAB * 3 * DM];        // lm_head weights

__device__ __forceinline__ uint32_t smem_u32(const void* p) {
    uint32_t a;
    asm("{ .reg .u64 t; cvta.to.shared.u64 t, %1; cvt.u32.u64 %0, t; }"
        : "=r"(a) : "l"(p));
    return a;
}

// ============ warp-MMA bf16 GEMM: C[M,N] = A[M,Kp] * B[N,Kp]^T ===============
// 128x128x32 CTA tile, 8 warps (4x2), warp tile 32x64, ldmatrix + mma.m16n8k16.
#define ASTRIDE 40   // smem row stride in bf16 elems (80B: conflict-free ldmatrix)

__global__ void __launch_bounds__(256) gemm_bf16(
    const __nv_bfloat16* __restrict__ A, const __nv_bfloat16* __restrict__ B,
    float* __restrict__ C, int Ntot, int Kp, int ldc)
{
    __shared__ __nv_bfloat16 As[128 * ASTRIDE];
    __shared__ __nv_bfloat16 Bs[128 * ASTRIDE];

    int tid = threadIdx.x;
    int lane = tid & 31, wid = tid >> 5;
    int warp_m = wid >> 1, warp_n = wid & 1;
    int bm = blockIdx.y << 7, bn = blockIdx.x << 7;
    int nstage = Kp >> 5;

    // global load indexing: each thread 2 uint4 per tile (rows rr, rr+64)
    int rr = tid >> 2, ch = (tid & 3) * 8;
    const __nv_bfloat16* Ag0 = A + (size_t)(bm + rr) * Kp + ch;
    const __nv_bfloat16* Ag1 = Ag0 + (size_t)64 * Kp;
    int bnr0 = bn + rr, bnr1 = bnr0 + 64;
    const __nv_bfloat16* Bg0 = B + (size_t)bnr0 * Kp + ch;
    const __nv_bfloat16* Bg1 = Bg0 + (size_t)64 * Kp;
    bool v0 = bnr0 < Ntot, v1 = bnr1 < Ntot;
    __nv_bfloat16* sA0 = &As[rr * ASTRIDE + ch];
    __nv_bfloat16* sA1 = sA0 + 64 * ASTRIDE;
    __nv_bfloat16* sB0 = &Bs[rr * ASTRIDE + ch];
    __nv_bfloat16* sB1 = sB0 + 64 * ASTRIDE;

    // ldmatrix per-lane shared addresses
    int lrow = lane & 7, g = lane >> 3;
    uint32_t aAddr[2], bAddr[4];
#pragma unroll
    for (int mt = 0; mt < 2; mt++) {
        int row = warp_m * 32 + mt * 16 + (g & 1) * 8 + lrow;
        int col = (g >> 1) * 8;
        aAddr[mt] = smem_u32(As) + (row * ASTRIDE + col) * 2;
    }
#pragma unroll
    for (int j = 0; j < 4; j++) {
        int row = warp_n * 64 + j * 16 + (g >> 1) * 8 + lrow;
        int col = (g & 1) * 8;
        bAddr[j] = smem_u32(Bs) + (row * ASTRIDE + col) * 2;
    }

    float acc[2][8][4];
#pragma unroll
    for (int mt = 0; mt < 2; mt++)
#pragma unroll
        for (int nt = 0; nt < 8; nt++)
#pragma unroll
            for (int e = 0; e < 4; e++) acc[mt][nt][e] = 0.f;

    const uint4 Z = make_uint4(0u, 0u, 0u, 0u);
    // prologue: stage 0
    uint4 ra0 = *(const uint4*)Ag0;
    uint4 ra1 = *(const uint4*)Ag1;
    uint4 rb0 = v0 ? *(const uint4*)Bg0 : Z;
    uint4 rb1 = v1 ? *(const uint4*)Bg1 : Z;
    *(uint4*)sA0 = ra0; *(uint4*)sA1 = ra1;
    *(uint4*)sB0 = rb0; *(uint4*)sB1 = rb1;
    __syncthreads();

    for (int ks = 0; ks < nstage; ks++) {
        if (ks + 1 < nstage) {
            int off = (ks + 1) * 32;
            ra0 = *(const uint4*)(Ag0 + off);
            ra1 = *(const uint4*)(Ag1 + off);
            rb0 = v0 ? *(const uint4*)(Bg0 + off) : Z;
            rb1 = v1 ? *(const uint4*)(Bg1 + off) : Z;
        }
#pragma unroll
        for (int kst = 0; kst < 2; kst++) {
            uint32_t af[2][4];
#pragma unroll
            for (int mt = 0; mt < 2; mt++) {
                asm volatile(
                    "ldmatrix.sync.aligned.m8n8.x4.shared.b16 {%0,%1,%2,%3}, [%4];"
                    : "=r"(af[mt][0]), "=r"(af[mt][1]),
                      "=r"(af[mt][2]), "=r"(af[mt][3])
                    : "r"(aAddr[mt] + kst * 32));
            }
            uint32_t bf[8][2];
#pragma unroll
            for (int j = 0; j < 4; j++) {
                asm volatile(
                    "ldmatrix.sync.aligned.m8n8.x4.shared.b16 {%0,%1,%2,%3}, [%4];"
                    : "=r"(bf[2 * j][0]), "=r"(bf[2 * j][1]),
                      "=r"(bf[2 * j + 1][0]), "=r"(bf[2 * j + 1][1])
                    : "r"(bAddr[j] + kst * 32));
            }
#pragma unroll
            for (int mt = 0; mt < 2; mt++)
#pragma unroll
                for (int nt = 0; nt < 8; nt++) {
                    asm volatile(
                        "mma.sync.aligned.m16n8k16.row.col.f32.bf16.bf16.f32 "
                        "{%0,%1,%2,%3}, {%4,%5,%6,%7}, {%8,%9}, {%0,%1,%2,%3};"
                        : "+f"(acc[mt][nt][0]), "+f"(acc[mt][nt][1]),
                          "+f"(acc[mt][nt][2]), "+f"(acc[mt][nt][3])
                        : "r"(af[mt][0]), "r"(af[mt][1]),
                          "r"(af[mt][2]), "r"(af[mt][3]),
                          "r"(bf[nt][0]), "r"(bf[nt][1]));
                }
        }
        __syncthreads();
        if (ks + 1 < nstage) {
            *(uint4*)sA0 = ra0; *(uint4*)sA1 = ra1;
            *(uint4*)sB0 = rb0; *(uint4*)sB1 = rb1;
            __syncthreads();
        }
    }

    // epilogue
#pragma unroll
    for (int mt = 0; mt < 2; mt++) {
        int m0 = bm + warp_m * 32 + mt * 16 + (lane >> 2);
#pragma unroll
        for (int nt = 0; nt < 8; nt++) {
            int n0 = bn + warp_n * 64 + nt * 8 + (lane & 3) * 2;
            if (n0 < Ntot) {
                *(float2*)&C[(size_t)m0 * ldc + n0] =
                    make_float2(acc[mt][nt][0], acc[mt][nt][1]);
                *(float2*)&C[(size_t)(m0 + 8) * ldc + n0] =
                    make_float2(acc[mt][nt][2], acc[mt][nt][3]);
            }
        }
    }
}

// ------------- fp32 -> bf16 3-term split conversion ---------------------------
// dst row layout (3K wide): A uses lo_block=1 ([hi|lo|hi]); B lo_block=2 ([hi|hi|lo]).
__global__ void k_cvt3(const float* __restrict__ src, __nv_bfloat16* __restrict__ dst,
                       int K, int lo_block, int total)
{
    int i = blockIdx.x * blockDim.x + threadIdx.x;
    if (i >= total) return;
    int r = i / K, k = i - r * K;
    float x = src[i];
    __nv_bfloat16 hi = __float2bfloat16(x);
    __nv_bfloat16 lo = __float2bfloat16(x - __bfloat162float(hi));
    size_t base = (size_t)r * 3 * K + k;
    dst[base]                 = (lo_block == 0) ? lo : hi;
    dst[base + K]             = (lo_block == 1) ? lo : hi;
    dst[base + 2 * (size_t)K] = (lo_block == 2) ? lo : hi;
}

// ---------------- init: embedding gather + zero residual ---------------------
__global__ void k_init(const int* __restrict__ ids, const float* __restrict__ emb)
{
    int i = blockIdx.x * blockDim.x + threadIdx.x;
    if (i < SEQ * DM) {
        int t = i / DM, c = i - t * DM;
        g_x[i]   = emb[(size_t)ids[t] * DM + c];
        g_res[i] = 0.f;
    }
}

__global__ void k_copy_lres()
{
    int i = blockIdx.x * blockDim.x + threadIdx.x;
    if (i < SEQ * DM) g_lres[i] = g_res[i];
}

__global__ void k_add_lres()
{
    int i = blockIdx.x * blockDim.x + threadIdx.x;
    if (i < SEQ * DM) g_res[i] += g_lres[i];
}

// ---------------- fused residual add + RMSNorm --------------------------------
__global__ void __launch_bounds__(256) k_addnorm(const float* __restrict__ w)
{
    int r = blockIdx.x;
    int tid = threadIdx.x;
    float v[3];
    float ss = 0.f;
#pragma unroll
    for (int j = 0; j < 3; j++) {
        int c = tid + j * 256;
        float t = g_x[r * DM + c] + g_res[r * DM + c];
        g_res[r * DM + c] = t;
        v[j] = t;
        ss += t * t;
    }
#pragma unroll
    for (int o = 16; o; o >>= 1) ss += __shfl_xor_sync(0xffffffffu, ss, o);
    __shared__ float red[8];
    __shared__ float scale;
    if ((tid & 31) == 0) red[tid >> 5] = ss;
    __syncthreads();
    if (tid == 0) {
        float s = 0.f;
#pragma unroll
        for (int i = 0; i < 8; i++) s += red[i];
        scale = rsqrtf(s * (1.0f / DM) + 1e-5f);
    }
    __syncthreads();
    float sc = scale;
#pragma unroll
    for (int j = 0; j < 3; j++) {
        int c = tid + j * 256;
        g_h[r * DM + c] = v[j] * sc * w[c];
    }
}

// ---------------- SIMT SGEMM (dt_proj only, K=48) -----------------------------
__global__ void __launch_bounds__(256) sgemm_nt(
    const float* __restrict__ A, const float* __restrict__ B, float* __restrict__ C,
    int N, int K, int lda, int ldb, int ldc,
    const float* __restrict__ bias, int mode)
{
    __shared__ float As[8][132];
    __shared__ float Bs[8][132];
    int tid = threadIdx.x;
    int bm = blockIdx.y << 7;
    int bn = blockIdx.x << 7;
    int lr = tid >> 1;
    int lk = (tid & 1) << 2;
    const float* Ag = A + (size_t)(bm + lr) * lda + lk;
    int brow = bn + lr;
    const float* Bg = B + (size_t)brow * ldb + lk;
    bool bvalid = brow < N;
    int tx = tid & 15, ty = tid >> 4;

    float acc[8][8];
#pragma unroll
    for (int i = 0; i < 8; i++)
#pragma unroll
        for (int j = 0; j < 8; j++) acc[i][j] = 0.f;

    for (int k0 = 0; k0 < K; k0 += 8) {
        float4 av = *(const float4*)(Ag + k0);
        float4 bv = make_float4(0.f, 0.f, 0.f, 0.f);
        if (bvalid) bv = *(const float4*)(Bg + k0);
        As[lk + 0][lr] = av.x; As[lk + 1][lr] = av.y;
        As[lk + 2][lr] = av.z; As[lk + 3][lr] = av.w;
        Bs[lk + 0][lr] = bv.x; Bs[lk + 1][lr] = bv.y;
        Bs[lk + 2][lr] = bv.z; Bs[lk + 3][lr] = bv.w;
        __syncthreads();
#pragma unroll
        for (int k = 0; k < 8; k++) {
            float4 a0 = *(const float4*)&As[k][ty << 3];
            float4 a1 = *(const float4*)&As[k][(ty << 3) + 4];
            float4 b0 = *(const float4*)&Bs[k][tx << 3];
            float4 b1 = *(const float4*)&Bs[k][(tx << 3) + 4];
            float ar[8] = {a0.x, a0.y, a0.z, a0.w, a1.x, a1.y, a1.z, a1.w};
            float br[8] = {b0.x, b0.y, b0.z, b0.w, b1.x, b1.y, b1.z, b1.w};
#pragma unroll
            for (int i = 0; i < 8; i++)
#pragma unroll
                for (int j = 0; j < 8; j++)
                    acc[i][j] = fmaf(ar[i], br[j], acc[i][j]);
        }
        __syncthreads();
    }

#pragma unroll
    for (int i = 0; i < 8; i++) {
        int m = bm + (ty << 3) + i;
#pragma unroll
        for (int j = 0; j < 8; j++) {
            int n = bn + (tx << 3) + j;
            if (n < N) {
                float vv = acc[i][j];
                if (mode == 1) {
                    vv += bias[n];
                    vv = (vv > 15.f) ? vv : log1pf(__expf(vv));
                }
                C[(size_t)m * ldc + n] = vv;
            }
        }
    }
}

// ---------------- depthwise causal conv (K=4) + SiLU --------------------------
__global__ void k_conv(const float* __restrict__ cw, const float* __restrict__ cb)
{
    int i = blockIdx.x * blockDim.x + threadIdx.x;
    if (i >= SEQ * DI) return;
    int t = i / DI, d = i - t * DI;
    float s = cb[d];
    const float* w = cw + d * 4;
#pragma unroll
    for (int j = 0; j < 4; j++) {
        int tt = t - 3 + j;
        if (tt >= 0) s = fmaf(w[j], g_xz[tt * (2 * DI) + d], s);
    }
    g_xs[i] = s / (1.f + __expf(-s));
}

// ---------------- x_proj: dbc[m, 0:80] = xs[m,:] @ x_proj_w^T -----------------
__global__ void __launch_bounds__(256) k_xproj(const float* __restrict__ Bw)
{
    int m = blockIdx.x;
    __shared__ float ar[DI];
    for (int i = threadIdx.x; i < DI; i += 256) ar[i] = g_xs[m * DI + i];
    __syncthreads();
    int w = threadIdx.x >> 5, lane = threadIdx.x & 31;
    for (int n = w; n < 80; n += 8) {
        const float* bp = Bw + n * DI;
        float acc = 0.f;
        for (int k = lane; k < DI; k += 32) acc = fmaf(ar[k], bp[k], acc);
#pragma unroll
        for (int o = 16; o; o >>= 1) acc += __shfl_xor_sync(0xffffffffu, acc, o);
        if (lane == 0) g_dbc[m * 80 + n] = acc;
    }
}

// ---------------- selective scan + D skip + SiLU gate --------------------------
__global__ void __launch_bounds__(256) k_scan(const float* __restrict__ Alog,
                                              const float* __restrict__ Dp)
{
    int tid = threadIdx.x;
    int grp = tid >> 4;
    int n = tid & 15;
    int d = blockIdx.x * 16 + grp;

    float A  = -__expf(Alog[d * DS + n]);
    float Dd = Dp[d];
    float h = 0.f;

    const float* dtp = g_dt + d;
    const float* xsp = g_xs + d;
    const float* zp  = g_xz + DI + d;
    const float* bp  = g_dbc + 48 + n;
    const float* cp  = g_dbc + 64 + n;
    float* yo = g_yz + d;

    for (int t = 0; t < SEQ; t++) {
        float a  = dtp[t * DI];
        float x  = xsp[t * DI];
        float Bv = bp[t * 80];
        float Cv = cp[t * 80];
        float dA = __expf(a * A);
        h = fmaf(dA, h, a * Bv * x);
        float yp = h * Cv;
        yp += __shfl_xor_sync(0xffffffffu, yp, 8);
        yp += __shfl_xor_sync(0xffffffffu, yp, 4);
        yp += __shfl_xor_sync(0xffffffffu, yp, 2);
        yp += __shfl_xor_sync(0xffffffffu, yp, 1);
        if (n == 0) {
            float z = zp[t * 2 * DI];
            float y = fmaf(Dd, x, yp);
            yo[t * DI] = y * (z / (1.f + __expf(-z)));
        }
    }
}

// ---------------- host orchestration ------------------------------------------
extern "C" void kernel_launch(void* const* d_in, const int* in_sizes, int n_in,
                              void* d_out, int out_size)
{
    (void)in_sizes; (void)n_in; (void)out_size;
    const int*   ids   = (const int*)  d_in[0];
    const float* emb   = (const float*)d_in[1];
    const float* inw   = (const float*)d_in[2];
    const float* convw = (const float*)d_in[3];
    const float* convb = (const float*)d_in[4];
    const float* xpw   = (const float*)d_in[5];
    const float* dtw   = (const float*)d_in[6];
    const float* dtb   = (const float*)d_in[7];
    const float* alog  = (const float*)d_in[8];
    const float* Dp    = (const float*)d_in[9];
    const float* outw  = (const float*)d_in[10];
    const float* nw    = (const float*)d_in[11];
    const float* nfw   = (const float*)d_in[12];
    const float* lmw   = (const float*)d_in[13];
    float* out = (float*)d_out;

    static float *p_h = nullptr, *p_xz = nullptr, *p_dbc = nullptr,
                 *p_dt = nullptr, *p_yz = nullptr, *p_x = nullptr;
    static __nv_bfloat16 *p_abf = nullptr, *p_wbf = nullptr, *p_lmbf = nullptr;
    if (!p_h) {
        cudaGetSymbolAddress((void**)&p_h,    g_h);
        cudaGetSymbolAddress((void**)&p_xz,   g_xz);
        cudaGetSymbolAddress((void**)&p_dbc,  g_dbc);
        cudaGetSymbolAddress((void**)&p_dt,   g_dt);
        cudaGetSymbolAddress((void**)&p_yz,   g_yz);
        cudaGetSymbolAddress((void**)&p_x,    g_x);
        cudaGetSymbolAddress((void**)&p_abf,  g_abf);
        cudaGetSymbolAddress((void**)&p_wbf,  g_wbf);
        cudaGetSymbolAddress((void**)&p_lmbf, g_lmbf);
    }

    const int EW = (SEQ * DM) / 256;

    k_init<<<EW, 256>>>(ids, emb);

    // lm_head weight conversion (independent of the layer loop; do it up front)
    {
        int total = VOCAB * DM;
        k_cvt3<<<(total + 255) / 256, 256>>>(lmw, p_lmbf, DM, 2, total);
    }

    for (int step = 0; step < 28; step++) {
        int li = (step < 22) ? step : 22 + ((step - 22) & 1);
        if (step >= 22 && ((step - 22) & 1) == 0)
            k_copy_lres<<<EW, 256>>>();

        // residual add + norm -> g_h
        k_addnorm<<<SEQ, 256>>>(nw + (size_t)li * DM);

        // in_proj (bf16 3-term): g_xz = g_h @ W^T  (1024 x 3072, K'=2304)
        k_cvt3<<<(SEQ * DM + 255) / 256, 256>>>(p_h, p_abf, DM, 1, SEQ * DM);
        {
            int total = 2 * DI * DM;
            k_cvt3<<<(total + 255) / 256, 256>>>(inw + (size_t)li * 2 * DI * DM,
                                                 p_wbf, DM, 2, total);
        }
        gemm_bf16<<<dim3((2 * DI) / 128, SEQ / 128), 256>>>(
            p_abf, p_wbf, p_xz, 2 * DI, 3 * DM, 2 * DI);

        // depthwise conv + silu -> g_xs
        k_conv<<<(SEQ * DI) / 256, 256>>>(convw + (size_t)li * DI * 4,
                                          convb + (size_t)li * DI);

        // x_proj -> g_dbc (1024 x 80, K=1536)
        k_xproj<<<SEQ, 256>>>(xpw + (size_t)li * 80 * DI);

        // dt = softplus(dbc[:, :48] @ dt_w^T + b)  (1024 x 1536, K=48) — SIMT
        sgemm_nt<<<dim3(DI / 128, SEQ / 128), 256>>>(
            p_dbc, dtw + (size_t)li * DI * DTR, p_dt,
            DI, DTR, 80, DTR, DI, dtb + (size_t)li * DI, 1);

        // selective scan + gate -> g_yz
        k_scan<<<DI / 16, 256>>>(alog + (size_t)li * DI * DS,
                                 Dp + (size_t)li * DI);

        // out_proj (bf16 3-term): g_x = g_yz @ W^T  (1024 x 768, K'=4608)
        k_cvt3<<<(SEQ * DI + 255) / 256, 256>>>(p_yz, p_abf, DI, 1, SEQ * DI);
        {
            int total = DM * DI;
            k_cvt3<<<(total + 255) / 256, 256>>>(outw + (size_t)li * DM * DI,
                                                 p_wbf, DI, 2, total);
        }
        gemm_bf16<<<dim3(DM / 128, SEQ / 128), 256>>>(
            p_abf, p_wbf, p_x, DM, 3 * DI, DM);

        if (step >= 22 && ((step - 22) & 1) == 1)
            k_add_lres<<<EW, 256>>>();
    }

    // final fused add-norm -> g_h
    k_addnorm<<<SEQ, 256>>>(nfw);

    // lm_head (bf16 3-term): out = g_h @ lm_head_w^T  (1024 x 50280, K'=2304)
    k_cvt3<<<(SEQ * DM + 255) / 256, 256>>>(p_h, p_abf, DM, 1, SEQ * DM);
    gemm_bf16<<<dim3((VOCAB + 127) / 128, SEQ / 128), 256>>>(
        p_abf, p_lmbf, out, VOCAB, 3 * DM, VOCAB);
}

// round 5
// speedup vs baseline: 2.5946x; 1.8746x over previous
#include <cuda_runtime.h>
#include <cuda_bf16.h>
#include <math.h>
#include <stdint.h>

// Model dims
#define SEQ   1024
#define DM    768
#define DI    1536
#define DS    16
#define DTR   48
#define VOCAB 50280
#define NLAYER 24

// ---------------- scratch buffers (device globals; no allocation) ------------
__device__ float g_x  [SEQ * DM];
__device__ float g_res[SEQ * DM];
__device__ float g_lres[SEQ * DM];
__device__ float g_xz [SEQ * 2 * DI];
__device__ float g_xs [SEQ * DI];
__device__ float g_dbc[SEQ * 80];
__device__ float g_dt [SEQ * DI];

// bf16 3-term split buffers
__device__ __nv_bfloat16 g_abf [SEQ * 3 * DI];                 // activation triples
__device__ __nv_bfloat16 g_wbf_in [(size_t)NLAYER * 3072 * 2304];
__device__ __nv_bfloat16 g_wbf_out[(size_t)NLAYER * 768 * 4608];
__device__ __nv_bfloat16 g_lmbf[(size_t)VOCAB * 2304];

__device__ __forceinline__ uint32_t smem_u32(const void* p) {
    uint32_t a;
    asm("{ .reg .u64 t; cvta.to.shared.u64 t, %1; cvt.u32.u64 %0, t; }"
        : "=r"(a) : "l"(p));
    return a;
}
__device__ __forceinline__ void cp16(uint32_t dst, const void* src) {
    asm volatile("cp.async.cg.shared.global [%0], [%1], 16;"
                 :: "r"(dst), "l"(src));
}
__device__ __forceinline__ void cp_commit() {
    asm volatile("cp.async.commit_group;" ::: "memory");
}
__device__ __forceinline__ void cp_wait1() {
    asm volatile("cp.async.wait_group 1;" ::: "memory");
}

// ============ warp-MMA bf16 GEMM: C[M,N] = A[M,Kp] * B[N,Kp]^T ===============
// 128x128x32 CTA tile, 8 warps (4x2), warp tile 32x64, cp.async 3-stage pipe.
#define ASTR 56                   // smem row stride elems (112B): 16B-aligned,
                                  // 7r mod 8 distinct -> conflict-free ldmatrix
#define STAGE_BYTES (2 * 128 * ASTR * 2)   // A half + B half = 28672
#define GEMM_SMEM   (3 * STAGE_BYTES)      // 86016

__global__ void __launch_bounds__(256) gemm_bf16(
    const __nv_bfloat16* __restrict__ A, const __nv_bfloat16* __restrict__ B,
    float* __restrict__ C, int Ntot, int Kp, int ldc)
{
    extern __shared__ __align__(16) char smem[];
    uint32_t smemU = smem_u32(smem);

    int tid = threadIdx.x;
    int lane = tid & 31, wid = tid >> 5;
    int warp_m = wid >> 1, warp_n = wid & 1;
    int bm = blockIdx.y << 7, bn = blockIdx.x << 7;
    int nstage = Kp >> 5;

    // cp.async mapping: 512 chunks of 16B per half; thread owns 2 consecutive
    int cid = tid * 2;
    int crow = cid >> 2;              // 0..127
    int ccol = (cid & 3) * 16;        // byte col within 64B row: 0 or 32
    size_t KpB = (size_t)Kp * 2;
    const char* Asrc = (const char*)A + (size_t)(bm + crow) * KpB + ccol;
    int brow = bn + crow; if (brow >= Ntot) brow = Ntot - 1;
    const char* Bsrc = (const char*)B + (size_t)brow * KpB + ccol;
    uint32_t dA = smemU + crow * 112 + ccol;
    uint32_t dB = dA + 128 * 112;

    // ldmatrix per-lane relative addresses (within a stage)
    int lrow = lane & 7, g = lane >> 3;
    uint32_t aRel[2], bRel[4];
#pragma unroll
    for (int mt = 0; mt < 2; mt++) {
        int row = warp_m * 32 + mt * 16 + (g & 1) * 8 + lrow;
        int col = (g >> 1) * 8;
        aRel[mt] = smemU + row * 112 + col * 2;
    }
#pragma unroll
    for (int j = 0; j < 4; j++) {
        int row = warp_n * 64 + j * 16 + (g >> 1) * 8 + lrow;
        int col = (g & 1) * 8;
        bRel[j] = smemU + 128 * 112 + row * 112 + col * 2;
    }

    float acc[2][8][4];
#pragma unroll
    for (int mt = 0; mt < 2; mt++)
#pragma unroll
        for (int nt = 0; nt < 8; nt++)
#pragma unroll
            for (int e = 0; e < 4; e++) acc[mt][nt][e] = 0.f;

    // prologue: stages 0,1
#pragma unroll
    for (int s = 0; s < 2; s++) {
        size_t ko = (size_t)s * 64;
        uint32_t sb = s * STAGE_BYTES;
        cp16(dA + sb, Asrc + ko);       cp16(dA + sb + 16, Asrc + ko + 16);
        cp16(dB + sb, Bsrc + ko);       cp16(dB + sb + 16, Bsrc + ko + 16);
        cp_commit();
    }

    int s = 0;            // stage of current compute
    for (int ks = 0; ks < nstage; ks++) {
        cp_wait1();
        __syncthreads();

        // issue stage ks+2 (safe: all warps done computing that buffer)
        if (ks + 2 < nstage) {
            int sn = s + 2; if (sn >= 3) sn -= 3;
            size_t ko = (size_t)(ks + 2) * 64;
            uint32_t sb = sn * STAGE_BYTES;
            cp16(dA + sb, Asrc + ko);   cp16(dA + sb + 16, Asrc + ko + 16);
            cp16(dB + sb, Bsrc + ko);   cp16(dB + sb + 16, Bsrc + ko + 16);
        }
        cp_commit();

        uint32_t sb = s * STAGE_BYTES;
#pragma unroll
        for (int kst = 0; kst < 2; kst++) {
            uint32_t af[2][4];
#pragma unroll
            for (int mt = 0; mt < 2; mt++) {
                asm volatile(
                    "ldmatrix.sync.aligned.m8n8.x4.shared.b16 {%0,%1,%2,%3}, [%4];"
                    : "=r"(af[mt][0]), "=r"(af[mt][1]),
                      "=r"(af[mt][2]), "=r"(af[mt][3])
                    : "r"(aRel[mt] + sb + kst * 32));
            }
            uint32_t bf[8][2];
#pragma unroll
            for (int j = 0; j < 4; j++) {
                asm volatile(
                    "ldmatrix.sync.aligned.m8n8.x4.shared.b16 {%0,%1,%2,%3}, [%4];"
                    : "=r"(bf[2 * j][0]), "=r"(bf[2 * j][1]),
                      "=r"(bf[2 * j + 1][0]), "=r"(bf[2 * j + 1][1])
                    : "r"(bRel[j] + sb + kst * 32));
            }
#pragma unroll
            for (int mt = 0; mt < 2; mt++)
#pragma unroll
                for (int nt = 0; nt < 8; nt++) {
                    asm volatile(
                        "mma.sync.aligned.m16n8k16.row.col.f32.bf16.bf16.f32 "
                        "{%0,%1,%2,%3}, {%4,%5,%6,%7}, {%8,%9}, {%0,%1,%2,%3};"
                        : "+f"(acc[mt][nt][0]), "+f"(acc[mt][nt][1]),
                          "+f"(acc[mt][nt][2]), "+f"(acc[mt][nt][3])
                        : "r"(af[mt][0]), "r"(af[mt][1]),
                          "r"(af[mt][2]), "r"(af[mt][3]),
                          "r"(bf[nt][0]), "r"(bf[nt][1]));
                }
        }
        if (++s >= 3) s -= 3;
    }

    // epilogue
#pragma unroll
    for (int mt = 0; mt < 2; mt++) {
        int m0 = bm + warp_m * 32 + mt * 16 + (lane >> 2);
#pragma unroll
        for (int nt = 0; nt < 8; nt++) {
            int n0 = bn + warp_n * 64 + nt * 8 + (lane & 3) * 2;
            if (n0 < Ntot) {
                *(float2*)&C[(size_t)m0 * ldc + n0] =
                    make_float2(acc[mt][nt][0], acc[mt][nt][1]);
                *(float2*)&C[(size_t)(m0 + 8) * ldc + n0] =
                    make_float2(acc[mt][nt][2], acc[mt][nt][3]);
            }
        }
    }
}

// ------------- fp32 -> bf16 3-term split conversion (weights) -----------------
// dst row layout (3K wide): lo in block lo_block. A:[hi|lo|hi]=1, B:[hi|hi|lo]=2.
__global__ void k_cvt3(const float* __restrict__ src, __nv_bfloat16* __restrict__ dst,
                       int K, int lo_block, int total)
{
    int i = blockIdx.x * blockDim.x + threadIdx.x;
    if (i >= total) return;
    int r = i / K, k = i - r * K;
    float x = src[i];
    __nv_bfloat16 hi = __float2bfloat16(x);
    __nv_bfloat16 lo = __float2bfloat16(x - __bfloat162float(hi));
    size_t base = (size_t)r * 3 * K + k;
    dst[base]                 = (lo_block == 0) ? lo : hi;
    dst[base + K]             = (lo_block == 1) ? lo : hi;
    dst[base + 2 * (size_t)K] = (lo_block == 2) ? lo : hi;
}

// ---------------- init: embedding gather + zero residual ---------------------
__global__ void k_init(const int* __restrict__ ids, const float* __restrict__ emb)
{
    int i = blockIdx.x * blockDim.x + threadIdx.x;
    if (i < SEQ * DM) {
        int t = i / DM, c = i - t * DM;
        g_x[i]   = emb[(size_t)ids[t] * DM + c];
        g_res[i] = 0.f;
    }
}

__global__ void k_copy_lres()
{
    int i = blockIdx.x * blockDim.x + threadIdx.x;
    if (i < SEQ * DM) g_lres[i] = g_res[i];
}

__global__ void k_add_lres()
{
    int i = blockIdx.x * blockDim.x + threadIdx.x;
    if (i < SEQ * DM) g_res[i] += g_lres[i];
}

// ------- fused residual add + RMSNorm + bf16 triple split ([hi|lo|hi]) --------
__global__ void __launch_bounds__(256) k_addnorm(const float* __restrict__ w)
{
    int r = blockIdx.x;
    int tid = threadIdx.x;
    float v[3];
    float ss = 0.f;
#pragma unroll
    for (int j = 0; j < 3; j++) {
        int c = tid + j * 256;
        float t = g_x[r * DM + c] + g_res[r * DM + c];
        g_res[r * DM + c] = t;
        v[j] = t;
        ss += t * t;
    }
#pragma unroll
    for (int o = 16; o; o >>= 1) ss += __shfl_xor_sync(0xffffffffu, ss, o);
    __shared__ float red[8];
    __shared__ float scale;
    if ((tid & 31) == 0) red[tid >> 5] = ss;
    __syncthreads();
    if (tid == 0) {
        float s = 0.f;
#pragma unroll
        for (int i = 0; i < 8; i++) s += red[i];
        scale = rsqrtf(s * (1.0f / DM) + 1e-5f);
    }
    __syncthreads();
    float sc = scale;
#pragma unroll
    for (int j = 0; j < 3; j++) {
        int c = tid + j * 256;
        float x = v[j] * sc * w[c];
        __nv_bfloat16 hi = __float2bfloat16(x);
        __nv_bfloat16 lo = __float2bfloat16(x - __bfloat162float(hi));
        size_t base = (size_t)r * 2304 + c;
        g_abf[base]        = hi;
        g_abf[base + 768]  = lo;
        g_abf[base + 1536] = hi;
    }
}

// ---------------- SIMT SGEMM (dt_proj only, K=48) -----------------------------
__global__ void __launch_bounds__(256) sgemm_nt(
    const float* __restrict__ A, const float* __restrict__ B, float* __restrict__ C,
    int N, int K, int lda, int ldb, int ldc,
    const float* __restrict__ bias, int mode)
{
    __shared__ float As[8][132];
    __shared__ float Bs[8][132];
    int tid = threadIdx.x;
    int bm = blockIdx.y << 7;
    int bn = blockIdx.x << 7;
    int lr = tid >> 1;
    int lk = (tid & 1) << 2;
    const float* Ag = A + (size_t)(bm + lr) * lda + lk;
    int brow = bn + lr;
    const float* Bg = B + (size_t)brow * ldb + lk;
    bool bvalid = brow < N;
    int tx = tid & 15, ty = tid >> 4;

    float acc[8][8];
#pragma unroll
    for (int i = 0; i < 8; i++)
#pragma unroll
        for (int j = 0; j < 8; j++) acc[i][j] = 0.f;

    for (int k0 = 0; k0 < K; k0 += 8) {
        float4 av = *(const float4*)(Ag + k0);
        float4 bv = make_float4(0.f, 0.f, 0.f, 0.f);
        if (bvalid) bv = *(const float4*)(Bg + k0);
        As[lk + 0][lr] = av.x; As[lk + 1][lr] = av.y;
        As[lk + 2][lr] = av.z; As[lk + 3][lr] = av.w;
        Bs[lk + 0][lr] = bv.x; Bs[lk + 1][lr] = bv.y;
        Bs[lk + 2][lr] = bv.z; Bs[lk + 3][lr] = bv.w;
        __syncthreads();
#pragma unroll
        for (int k = 0; k < 8; k++) {
            float4 a0 = *(const float4*)&As[k][ty << 3];
            float4 a1 = *(const float4*)&As[k][(ty << 3) + 4];
            float4 b0 = *(const float4*)&Bs[k][tx << 3];
            float4 b1 = *(const float4*)&Bs[k][(tx << 3) + 4];
            float ar[8] = {a0.x, a0.y, a0.z, a0.w, a1.x, a1.y, a1.z, a1.w};
            float br[8] = {b0.x, b0.y, b0.z, b0.w, b1.x, b1.y, b1.z, b1.w};
#pragma unroll
            for (int i = 0; i < 8; i++)
#pragma unroll
                for (int j = 0; j < 8; j++)
                    acc[i][j] = fmaf(ar[i], br[j], acc[i][j]);
        }
        __syncthreads();
    }

#pragma unroll
    for (int i = 0; i < 8; i++) {
        int m = bm + (ty << 3) + i;
#pragma unroll
        for (int j = 0; j < 8; j++) {
            int n = bn + (tx << 3) + j;
            if (n < N) {
                float vv = acc[i][j];
                if (mode == 1) {
                    vv += bias[n];
                    vv = (vv > 15.f) ? vv : log1pf(__expf(vv));
                }
                C[(size_t)m * ldc + n] = vv;
            }
        }
    }
}

// ---------------- depthwise causal conv (K=4) + SiLU --------------------------
__global__ void k_conv(const float* __restrict__ cw, const float* __restrict__ cb)
{
    int i = blockIdx.x * blockDim.x + threadIdx.x;
    if (i >= SEQ * DI) return;
    int t = i / DI, d = i - t * DI;
    float s = cb[d];
    const float* w = cw + d * 4;
#pragma unroll
    for (int j = 0; j < 4; j++) {
        int tt = t - 3 + j;
        if (tt >= 0) s = fmaf(w[j], g_xz[tt * (2 * DI) + d], s);
    }
    g_xs[i] = s / (1.f + __expf(-s));
}

// ---------------- x_proj: dbc[m, 0:80] = xs[m,:] @ x_proj_w^T -----------------
__global__ void __launch_bounds__(256) k_xproj(const float* __restrict__ Bw)
{
    int m = blockIdx.x;
    __shared__ float ar[DI];
    for (int i = threadIdx.x; i < DI; i += 256) ar[i] = g_xs[m * DI + i];
    __syncthreads();
    int w = threadIdx.x >> 5, lane = threadIdx.x & 31;
    for (int n = w; n < 80; n += 8) {
        const float* bp = Bw + n * DI;
        float acc = 0.f;
        for (int k = lane; k < DI; k += 32) acc = fmaf(ar[k], bp[k], acc);
#pragma unroll
        for (int o = 16; o; o >>= 1) acc += __shfl_xor_sync(0xffffffffu, acc, o);
        if (lane == 0) g_dbc[m * 80 + n] = acc;
    }
}

// -------- selective scan + D skip + SiLU gate + bf16 triple output ------------
// thread = (channel d, state n); unroll-8 with register prefetch (MLP ~40).
#define SU 8
__global__ void __launch_bounds__(256) k_scan(const float* __restrict__ Alog,
                                              const float* __restrict__ Dp)
{
    int tid = threadIdx.x;
    int grp = tid >> 4;
    int n = tid & 15;
    int d = blockIdx.x * 16 + grp;

    float A  = -__expf(Alog[d * DS + n]);
    float Dd = Dp[d];
    float h = 0.f;

    const float* dtp = g_dt + d;
    const float* xsp = g_xs + d;
    const float* zp  = g_xz + DI + d;
    const float* bp  = g_dbc + 48 + n;
    const float* cp  = g_dbc + 64 + n;

    float pd[SU], px[SU], pb[SU], pc[SU], pz[SU];
#pragma unroll
    for (int i = 0; i < SU; i++) {
        pd[i] = dtp[i * DI];
        px[i] = xsp[i * DI];
        pb[i] = bp[i * 80];
        pc[i] = cp[i * 80];
        pz[i] = zp[i * 2 * DI];
    }

    for (int t0 = 0; t0 < SEQ; t0 += SU) {
        float cd[SU], cx[SU], cb[SU], cc[SU], cz[SU];
#pragma unroll
        for (int i = 0; i < SU; i++) {
            cd[i] = pd[i]; cx[i] = px[i]; cb[i] = pb[i];
            cc[i] = pc[i]; cz[i] = pz[i];
        }
        int tn = t0 + SU;
        if (tn < SEQ) {
#pragma unroll
            for (int i = 0; i < SU; i++) {
                pd[i] = dtp[(tn + i) * DI];
                px[i] = xsp[(tn + i) * DI];
                pb[i] = bp[(tn + i) * 80];
                pc[i] = cp[(tn + i) * 80];
                pz[i] = zp[(tn + i) * 2 * DI];
            }
        }
#pragma unroll
        for (int i = 0; i < SU; i++) {
            float a = cd[i], x = cx[i];
            float dA = __expf(a * A);
            h = fmaf(dA, h, a * cb[i] * x);
            float yp = h * cc[i];
            yp += __shfl_xor_sync(0xffffffffu, yp, 8);
            yp += __shfl_xor_sync(0xffffffffu, yp, 4);
            yp += __shfl_xor_sync(0xffffffffu, yp, 2);
            yp += __shfl_xor_sync(0xffffffffu, yp, 1);
            if (n == 0) {
                float z = cz[i];
                float y = fmaf(Dd, x, yp);
                float gv = y * (z / (1.f + __expf(-z)));
                __nv_bfloat16 hi = __float2bfloat16(gv);
                __nv_bfloat16 lo = __float2bfloat16(gv - __bfloat162float(hi));
                size_t base = (size_t)(t0 + i) * 4608 + d;
                g_abf[base]        = hi;
                g_abf[base + 1536] = lo;
                g_abf[base + 3072] = hi;
            }
        }
    }
}

// ---------------- host orchestration ------------------------------------------
extern "C" void kernel_launch(void* const* d_in, const int* in_sizes, int n_in,
                              void* d_out, int out_size)
{
    (void)in_sizes; (void)n_in; (void)out_size;
    const int*   ids   = (const int*)  d_in[0];
    const float* emb   = (const float*)d_in[1];
    const float* inw   = (const float*)d_in[2];
    const float* convw = (const float*)d_in[3];
    const float* convb = (const float*)d_in[4];
    const float* xpw   = (const float*)d_in[5];
    const float* dtw   = (const float*)d_in[6];
    const float* dtb   = (const float*)d_in[7];
    const float* alog  = (const float*)d_in[8];
    const float* Dp    = (const float*)d_in[9];
    const float* outw  = (const float*)d_in[10];
    const float* nw    = (const float*)d_in[11];
    const float* nfw   = (const float*)d_in[12];
    const float* lmw   = (const float*)d_in[13];
    float* out = (float*)d_out;

    static float *p_xz = nullptr, *p_dbc = nullptr, *p_dt = nullptr, *p_x = nullptr;
    static __nv_bfloat16 *p_abf = nullptr, *p_win = nullptr, *p_wout = nullptr,
                         *p_lmbf = nullptr;
    if (!p_xz) {
        cudaGetSymbolAddress((void**)&p_xz,   g_xz);
        cudaGetSymbolAddress((void**)&p_dbc,  g_dbc);
        cudaGetSymbolAddress((void**)&p_dt,   g_dt);
        cudaGetSymbolAddress((void**)&p_x,    g_x);
        cudaGetSymbolAddress((void**)&p_abf,  g_abf);
        cudaGetSymbolAddress((void**)&p_win,  g_wbf_in);
        cudaGetSymbolAddress((void**)&p_wout, g_wbf_out);
        cudaGetSymbolAddress((void**)&p_lmbf, g_lmbf);
        cudaFuncSetAttribute(gemm_bf16,
                             cudaFuncAttributeMaxDynamicSharedMemorySize,
                             GEMM_SMEM);
    }

    const int EW = (SEQ * DM) / 256;

    k_init<<<EW, 256>>>(ids, emb);

    // one-time weight conversions (whole stacks, layer-contiguous layout)
    {
        int tin = NLAYER * 3072 * DM;                 // 56.6M
        k_cvt3<<<(tin + 255) / 256, 256>>>(inw, p_win, DM, 2, tin);
        int tout = NLAYER * DM * DI;                  // 28.3M
        k_cvt3<<<(tout + 255) / 256, 256>>>(outw, p_wout, DI, 2, tout);
        int tlm = VOCAB * DM;
        k_cvt3<<<(tlm + 255) / 256, 256>>>(lmw, p_lmbf, DM, 2, tlm);
    }

    for (int step = 0; step < 28; step++) {
        int li = (step < 22) ? step : 22 + ((step - 22) & 1);
        if (step >= 22 && ((step - 22) & 1) == 0)
            k_copy_lres<<<EW, 256>>>();

        // residual add + norm + A-triple -> g_abf (1024 x 2304)
        k_addnorm<<<SEQ, 256>>>(nw + (size_t)li * DM);

        // in_proj: g_xz = abf @ win^T  (1024 x 3072, K'=2304)
        gemm_bf16<<<dim3(3072 / 128, SEQ / 128), 256, GEMM_SMEM>>>(
            p_abf, p_win + (size_t)li * 3072 * 2304, p_xz, 3072, 2304, 3072);

        // depthwise conv + silu -> g_xs
        k_conv<<<(SEQ * DI) / 256, 256>>>(convw + (size_t)li * DI * 4,
                                          convb + (size_t)li * DI);

        // x_proj -> g_dbc (1024 x 80, K=1536)
        k_xproj<<<SEQ, 256>>>(xpw + (size_t)li * 80 * DI);

        // dt = softplus(dbc[:, :48] @ dt_w^T + b)  (1024 x 1536, K=48) — SIMT
        sgemm_nt<<<dim3(DI / 128, SEQ / 128), 256>>>(
            p_dbc, dtw + (size_t)li * DI * DTR, p_dt,
            DI, DTR, 80, DTR, DI, dtb + (size_t)li * DI, 1);

        // selective scan + gate -> g_abf (out_proj A triple, 1024 x 4608)
        k_scan<<<DI / 16, 256>>>(alog + (size_t)li * DI * DS,
                                 Dp + (size_t)li * DI);

        // out_proj: g_x = abf @ wout^T  (1024 x 768, K'=4608)
        gemm_bf16<<<dim3(DM / 128, SEQ / 128), 256, GEMM_SMEM>>>(
            p_abf, p_wout + (size_t)li * DM * 4608, p_x, DM, 4608, DM);

        if (step >= 22 && ((step - 22) & 1) == 1)
            k_add_lres<<<EW, 256>>>();
    }

    // final fused add-norm + A-triple -> g_abf
    k_addnorm<<<SEQ, 256>>>(nfw);

    // lm_head: out = abf @ lmbf^T  (1024 x 50280, K'=2304)
    gemm_bf16<<<dim3((VOCAB + 127) / 128, SEQ / 128), 256, GEMM_SMEM>>>(
        p_abf, p_lmbf, out, VOCAB, 2304, VOCAB);
}